// round 1
// baseline (speedup 1.0000x reference)
#include <cuda_runtime.h>
#include <math.h>

// ---------------------------------------------------------------------------
// Problem constants (match reference)
// ---------------------------------------------------------------------------
#define B_ 4
#define T_ 2048
#define H_ 1024
#define DFF_ 4096
#define M_ (B_ * T_)      // 8192 tokens
#define HALF_ (H_ / 2)    // 512
#define ACT_TAU 0.99f
#define TARGET_DEPTH 2.5f
#define BUDGET_WEIGHT 0.01f

// ---------------------------------------------------------------------------
// Device scratch (no allocations allowed)
// ---------------------------------------------------------------------------
__device__ float g_h[(size_t)M_ * DFF_];     // FFN hidden (128 MB)
__device__ float g_x[(size_t)M_ * H_];       // current x   (32 MB)
__device__ float g_rh[(size_t)M_ * HALF_];   // router hidden (16 MB)
__device__ float g_w[M_];                    // per-token mix weight
__device__ float g_cum[M_];                  // cumulative_p
__device__ float g_still[M_];                // still_running
__device__ float g_wsum[M_];                 // weight_sum

// ---------------------------------------------------------------------------
// Helpers
// ---------------------------------------------------------------------------
__device__ __forceinline__ float gelu_exact(float v) {
    return 0.5f * v * (1.0f + erff(v * 0.70710678118654752440f));
}

// ---------------------------------------------------------------------------
// Tiled fp32 GEMM: C[M,N] = epi(A[M,K] * W[K,N] + bias[N])
// BM=128, BN=128, BK=16, 256 threads, 8x8 per-thread microtile.
// EPI: 0 = bias only, 1 = bias + GELU, 2 = bias + ACT soft mix
// All shapes in this problem are exact multiples of the tile sizes.
// ---------------------------------------------------------------------------
#define BM 128
#define BN 128
#define BK 16
#define TM 8
#define TN 8

template <int EPI>
__global__ __launch_bounds__(256, 2)
void gemm_kernel(const float* __restrict__ A, const float* __restrict__ W,
                 const float* __restrict__ bias, float* __restrict__ C,
                 int M, int N, int K,
                 const float* __restrict__ wmix, const float* __restrict__ xold)
{
    __shared__ __align__(16) float As[BK][BM + 4];  // +4 pad: kills store conflicts
    __shared__ __align__(16) float Bs[BK][BN];

    const int tid = threadIdx.x;
    const int row_base = blockIdx.y * BM;
    const int col_base = blockIdx.x * BN;

    const int tx = tid & 15;
    const int ty = tid >> 4;
    const int trow = ty * TM;
    const int tcol = tx * TN;

    float acc[TM][TN];
#pragma unroll
    for (int i = 0; i < TM; i++)
#pragma unroll
        for (int j = 0; j < TN; j++) acc[i][j] = 0.0f;

    for (int k0 = 0; k0 < K; k0 += BK) {
        // Load A tile: 128 rows x 16 cols = 512 float4, 2 per thread
#pragma unroll
        for (int s = 0; s < 2; s++) {
            int f = tid + 256 * s;
            int r = f >> 2;              // row in tile (0..127)
            int c4 = (f & 3) << 2;       // k offset {0,4,8,12}
            float4 a4 = *(const float4*)&A[(size_t)(row_base + r) * K + k0 + c4];
            As[c4 + 0][r] = a4.x;
            As[c4 + 1][r] = a4.y;
            As[c4 + 2][r] = a4.z;
            As[c4 + 3][r] = a4.w;
        }
        // Load B tile: 16 rows x 128 cols = 512 float4, 2 per thread
#pragma unroll
        for (int s = 0; s < 2; s++) {
            int f = tid + 256 * s;
            int r = f >> 5;              // k row (0..15)
            int c4 = (f & 31) << 2;      // col offset
            *(float4*)&Bs[r][c4] =
                *(const float4*)&W[(size_t)(k0 + r) * N + col_base + c4];
        }
        __syncthreads();

#pragma unroll
        for (int kk = 0; kk < BK; kk++) {
            float a_reg[TM], b_reg[TN];
            *(float4*)&a_reg[0] = *(const float4*)&As[kk][trow];
            *(float4*)&a_reg[4] = *(const float4*)&As[kk][trow + 4];
            *(float4*)&b_reg[0] = *(const float4*)&Bs[kk][tcol];
            *(float4*)&b_reg[4] = *(const float4*)&Bs[kk][tcol + 4];
#pragma unroll
            for (int i = 0; i < TM; i++)
#pragma unroll
                for (int j = 0; j < TN; j++)
                    acc[i][j] += a_reg[i] * b_reg[j];
        }
        __syncthreads();
    }

    // Epilogue
    float bia[TN];
#pragma unroll
    for (int j = 0; j < TN; j++) bia[j] = bias[col_base + tcol + j];

#pragma unroll
    for (int i = 0; i < TM; i++) {
        const int row = row_base + trow + i;
        float wv = 0.0f;
        if (EPI == 2) wv = wmix[row];
#pragma unroll
        for (int j = 0; j < TN; j++) {
            const int col = col_base + tcol + j;
            float v = acc[i][j] + bia[j];
            if (EPI == 1) v = gelu_exact(v);
            if (EPI == 2) {
                float xo = xold[(size_t)row * N + col];
                v = wv * v + (1.0f - wv) * xo;
            }
            C[(size_t)row * N + col] = v;
        }
    }
}

// ---------------------------------------------------------------------------
// Router head GEMV + ACT state update. One warp per token.
// logit = rh[t,:] . Rw2_i + Rb2_i ; p = sigmoid(logit) ; ACT remainder trick.
// ---------------------------------------------------------------------------
__global__ void router_act_kernel(const float* __restrict__ rh,
                                  const float* __restrict__ Rw2i,
                                  const float* __restrict__ Rb2i)
{
    const int warp = threadIdx.x >> 5;
    const int lane = threadIdx.x & 31;
    const int t = blockIdx.x * 8 + warp;
    if (t >= M_) return;

    const float* r = rh + (size_t)t * HALF_;
    float s = 0.0f;
#pragma unroll
    for (int k = lane; k < HALF_; k += 32) s += r[k] * Rw2i[k];
#pragma unroll
    for (int o = 16; o > 0; o >>= 1) s += __shfl_xor_sync(0xffffffffu, s, o);

    if (lane == 0) {
        const float logit = s + Rb2i[0];
        const float p = 1.0f / (1.0f + expf(-logit));
        const float cum = g_cum[t];
        const float still = g_still[t];
        const float rem = fmaxf(1.0f - cum, 0.0f);
        const bool halt = (cum + p >= ACT_TAU);
        const float w = (halt ? rem : p) * still;
        g_w[t] = w;
        g_cum[t] = cum + w;
        g_wsum[t] += w;
        g_still[t] = halt ? 0.0f : still;
    }
}

// ---------------------------------------------------------------------------
// Init ACT state (must run every launch: deterministic)
// ---------------------------------------------------------------------------
__global__ void init_state_kernel()
{
    const int t = blockIdx.x * 256 + threadIdx.x;
    if (t < M_) {
        g_cum[t] = 0.0f;
        g_still[t] = 1.0f;
        g_wsum[t] = 1.0f;
    }
}

// ---------------------------------------------------------------------------
// Budget loss: deterministic single-block reduction over g_wsum.
// ---------------------------------------------------------------------------
__global__ void budget_kernel(float* __restrict__ out)
{
    __shared__ float sh[256];
    float s = 0.0f;
    for (int t = threadIdx.x; t < M_; t += 256) s += g_wsum[t];
    sh[threadIdx.x] = s;
    __syncthreads();
#pragma unroll
    for (int o = 128; o > 0; o >>= 1) {
        if (threadIdx.x < o) sh[threadIdx.x] += sh[threadIdx.x + o];
        __syncthreads();
    }
    if (threadIdx.x == 0) {
        const float avg = sh[0] / (float)M_;
        const float d = avg - TARGET_DEPTH;
        const float rl = d > 0.0f ? d : 0.0f;
        out[0] = BUDGET_WEIGHT * rl * rl;
    }
}

// ---------------------------------------------------------------------------
// Launch
// ---------------------------------------------------------------------------
static void launch_gemm(int epi, const float* A, const float* W,
                        const float* bias, float* C, int M, int N, int K,
                        const float* wmix, const float* xold)
{
    dim3 grid(N / BN, M / BM);
    dim3 blk(256);
    switch (epi) {
        case 0: gemm_kernel<0><<<grid, blk>>>(A, W, bias, C, M, N, K, wmix, xold); break;
        case 1: gemm_kernel<1><<<grid, blk>>>(A, W, bias, C, M, N, K, wmix, xold); break;
        default: gemm_kernel<2><<<grid, blk>>>(A, W, bias, C, M, N, K, wmix, xold); break;
    }
}

extern "C" void kernel_launch(void* const* d_in, const int* in_sizes, int n_in,
                              void* d_out, int out_size)
{
    const float* x_in = (const float*)d_in[0];
    const float* Wb1  = (const float*)d_in[1];
    const float* bb1  = (const float*)d_in[2];
    const float* Wb2  = (const float*)d_in[3];
    const float* bb2  = (const float*)d_in[4];
    const float* Rw1  = (const float*)d_in[5];  // (3, 1025, 512)
    const float* Rb1  = (const float*)d_in[6];  // (3, 512)
    const float* Rw2  = (const float*)d_in[7];  // (3, 512, 1)
    const float* Rb2  = (const float*)d_in[8];  // (3, 1)
    float* out = (float*)d_out;

    float *gh, *gx, *grh, *gw;
    cudaGetSymbolAddress((void**)&gh,  g_h);
    cudaGetSymbolAddress((void**)&gx,  g_x);
    cudaGetSymbolAddress((void**)&grh, g_rh);
    cudaGetSymbolAddress((void**)&gw,  g_w);

    init_state_kernel<<<M_ / 256, 256>>>();

    // Mandatory first body pass: x = body(x_in)
    launch_gemm(1, x_in, Wb1, bb1, gh, M_, DFF_, H_, nullptr, nullptr);
    launch_gemm(0, gh, Wb2, bb2, gx, M_, H_, DFF_, nullptr, nullptr);

    for (int i = 0; i < 3; i++) {
        // Router: feat = [x, 0] -> last row of Rw1 multiplies zero, so K = H.
        const float* Rw1i = Rw1 + (size_t)i * 1025 * HALF_;
        const float* Rb1i = Rb1 + (size_t)i * HALF_;
        launch_gemm(1, gx, Rw1i, Rb1i, grh, M_, HALF_, H_, nullptr, nullptr);
        router_act_kernel<<<M_ / 8, 256>>>(grh, Rw2 + (size_t)i * HALF_, Rb2 + i);

        // Body + fused soft-depth mix: x = w*body(x) + (1-w)*x
        launch_gemm(1, gx, Wb1, bb1, gh, M_, DFF_, H_, nullptr, nullptr);
        float* dst = (i == 2) ? out : gx;   // final iteration writes output directly
        launch_gemm(2, gh, Wb2, bb2, dst, M_, H_, DFF_, gw, gx);
    }

    // Scalar budget loss at the tail of the output buffer.
    if (out_size > (int)((size_t)M_ * H_))
        budget_kernel<<<1, 256>>>(out + (size_t)M_ * H_);
}

// round 7
// speedup vs baseline: 2.7189x; 2.7189x over previous
#include <cuda_runtime.h>
#include <cuda_bf16.h>
#include <math.h>
#include <stdint.h>

// ---------------------------------------------------------------------------
// Problem constants
// ---------------------------------------------------------------------------
#define B_ 4
#define T_ 2048
#define H_ 1024
#define DFF_ 4096
#define M_ (B_ * T_)      // 8192 tokens
#define HALF_ (H_ / 2)    // 512
#define ACT_TAU 0.99f
#define TARGET_DEPTH 2.5f
#define BUDGET_WEIGHT 0.01f

// ---------------------------------------------------------------------------
// Device scratch (no allocations allowed)
// ---------------------------------------------------------------------------
__device__ float g_h[(size_t)M_ * DFF_];     // FFN hidden
__device__ float g_x[(size_t)M_ * H_];       // current x
__device__ float g_rh[(size_t)M_ * HALF_];   // router hidden
__device__ float g_w[M_];
__device__ float g_cum[M_];
__device__ float g_still[M_];
__device__ float g_wsum[M_];

// ---------------------------------------------------------------------------
// Helpers
// ---------------------------------------------------------------------------
__device__ __forceinline__ uint32_t smem_u32(const void* p) {
    uint32_t a;
    asm("{ .reg .u64 t; cvta.to.shared.u64 t, %1; cvt.u32.u64 %0, t; }"
        : "=r"(a) : "l"(p));
    return a;
}

__device__ __forceinline__ float gelu_exact(float v) {
    return 0.5f * v * (1.0f + erff(v * 0.70710678118654752440f));
}

__device__ __forceinline__ uint32_t pack2_bf16(float a, float b) {
    __nv_bfloat162 t = __floats2bfloat162_rn(a, b);
    return *reinterpret_cast<uint32_t*>(&t);
}

// ldmatrix: 4x 8x8 b16 tiles, non-transposed (A fragments)
__device__ __forceinline__ void ldsm_x4(uint32_t* r, uint32_t addr) {
    asm volatile("ldmatrix.sync.aligned.m8n8.x4.shared.b16 {%0,%1,%2,%3}, [%4];"
                 : "=r"(r[0]), "=r"(r[1]), "=r"(r[2]), "=r"(r[3]) : "r"(addr));
}
// ldmatrix transposed (B fragments, k-major from row-major [K][N])
__device__ __forceinline__ void ldsm_x4t(uint32_t* r, uint32_t addr) {
    asm volatile("ldmatrix.sync.aligned.m8n8.x4.trans.shared.b16 {%0,%1,%2,%3}, [%4];"
                 : "=r"(r[0]), "=r"(r[1]), "=r"(r[2]), "=r"(r[3]) : "r"(addr));
}

// mma m16n8k16 bf16 -> fp32 accum
__device__ __forceinline__ void mma_bf16(float* c, const uint32_t* a,
                                         uint32_t b0, uint32_t b1) {
    asm volatile(
        "mma.sync.aligned.m16n8k16.row.col.f32.bf16.bf16.f32 "
        "{%0,%1,%2,%3}, {%4,%5,%6,%7}, {%8,%9}, {%0,%1,%2,%3};"
        : "+f"(c[0]), "+f"(c[1]), "+f"(c[2]), "+f"(c[3])
        : "r"(a[0]), "r"(a[1]), "r"(a[2]), "r"(a[3]), "r"(b0), "r"(b1));
}

// ---------------------------------------------------------------------------
// HMMA GEMM: C[M,N] = epi(A[M,K] * W[K,N] + bias)    fp32 via bf16 3-split
// CTA 128x128, 8 warps (4x2), warp tile 32x64, K-chunk 32.
// SMEM: A (hi/lo) [128][40 bf16] stride 80B ; B (hi/lo) [32][136 bf16] stride 272B
// ---------------------------------------------------------------------------
#define TBM 128
#define TBN 128
#define TBK 32

#define A_STRIDE 80     // bytes per A smem row (40 bf16): conflict-free ldmatrix
#define B_STRIDE 272    // bytes per B smem row (136 bf16)
#define OFF_AH 0
#define OFF_AL 10240
#define OFF_BH 20480
#define OFF_BL 29184
#define SMEM_BYTES 37888

template <int EPI>
__global__ __launch_bounds__(256, 2)
void tgemm(const float* __restrict__ A, const float* __restrict__ W,
           const float* __restrict__ bias, float* __restrict__ C,
           int M, int N, int K,
           const float* __restrict__ wmix, const float* __restrict__ xold)
{
    extern __shared__ char smp[];
    const uint32_t sm = smem_u32(smp);

    const int tid = threadIdx.x;
    const int lane = tid & 31;
    const int warp = tid >> 5;
    const int warp_m = warp & 3;          // 4 warps along M  -> 32 rows each
    const int warp_n = warp >> 2;         // 2 warps along N  -> 64 cols each
    const int row_base = blockIdx.y * TBM;
    const int col_base = blockIdx.x * TBN;

    // fragment accumulators: [mi][nj][4]
    float acc[2][8][4];
#pragma unroll
    for (int i = 0; i < 2; i++)
#pragma unroll
        for (int j = 0; j < 8; j++)
#pragma unroll
            for (int k = 0; k < 4; k++) acc[i][j][k] = 0.0f;

    // per-lane ldmatrix base offsets
    // A: lanes 0-15 -> rows 0-15 (k 0-7), lanes 16-31 -> rows 0-15 (k 8-15)
    const uint32_t a_lane = (uint32_t)((warp_m * 32 + (lane & 15)) * A_STRIDE +
                                       (lane >> 4) * 16);
    // B: matrices: m0 k0-7/n0-7, m1 k8-15/n0-7, m2 k0-7/n8-15, m3 k8-15/n8-15
    const uint32_t b_lane = (uint32_t)((((lane >> 3) & 1) * 8 + (lane & 7)) * B_STRIDE +
                                       (warp_n * 64 + (lane >> 4) * 8) * 2);

    const int NC = K / TBK;
    for (int c = 0; c < NC; c++) {
        const int k0 = c * TBK;

        // ---- convert A chunk: 128 x 32 fp32 -> hi/lo bf16 ----
#pragma unroll
        for (int it = 0; it < 4; it++) {
            int f = tid + 256 * it;
            int r = f >> 3;              // 0..127
            int c4 = (f & 7) << 2;       // 0,4,..,28
            float4 v = *(const float4*)&A[(size_t)(row_base + r) * K + k0 + c4];
            __nv_bfloat16 hx = __float2bfloat16(v.x), hy = __float2bfloat16(v.y);
            __nv_bfloat16 hz = __float2bfloat16(v.z), hw = __float2bfloat16(v.w);
            uint2 hi;
            hi.x = ((uint32_t)__bfloat16_as_ushort(hy) << 16) | __bfloat16_as_ushort(hx);
            hi.y = ((uint32_t)__bfloat16_as_ushort(hw) << 16) | __bfloat16_as_ushort(hz);
            uint2 lo;
            lo.x = pack2_bf16(v.x - __bfloat162float(hx), v.y - __bfloat162float(hy));
            lo.y = pack2_bf16(v.z - __bfloat162float(hz), v.w - __bfloat162float(hw));
            uint32_t off = (uint32_t)(r * A_STRIDE + c4 * 2);
            *(uint2*)(smp + OFF_AH + off) = hi;
            *(uint2*)(smp + OFF_AL + off) = lo;
        }
        // ---- convert B chunk: 32 x 128 fp32 -> hi/lo bf16 ----
#pragma unroll
        for (int it = 0; it < 4; it++) {
            int f = tid + 256 * it;
            int kr = f >> 5;             // 0..31
            int nc4 = (f & 31) << 2;     // 0..124
            float4 v = *(const float4*)&W[(size_t)(k0 + kr) * N + col_base + nc4];
            __nv_bfloat16 hx = __float2bfloat16(v.x), hy = __float2bfloat16(v.y);
            __nv_bfloat16 hz = __float2bfloat16(v.z), hw = __float2bfloat16(v.w);
            uint2 hi;
            hi.x = ((uint32_t)__bfloat16_as_ushort(hy) << 16) | __bfloat16_as_ushort(hx);
            hi.y = ((uint32_t)__bfloat16_as_ushort(hw) << 16) | __bfloat16_as_ushort(hz);
            uint2 lo;
            lo.x = pack2_bf16(v.x - __bfloat162float(hx), v.y - __bfloat162float(hy));
            lo.y = pack2_bf16(v.z - __bfloat162float(hz), v.w - __bfloat162float(hw));
            uint32_t off = (uint32_t)(kr * B_STRIDE + nc4 * 2);
            *(uint2*)(smp + OFF_BH + off) = hi;
            *(uint2*)(smp + OFF_BL + off) = lo;
        }
        __syncthreads();

        // ---- MMA: 2 k16 steps, 3 precision passes ----
#pragma unroll
        for (int ks = 0; ks < 2; ks++) {
            uint32_t ah[2][4], al[2][4];
#pragma unroll
            for (int mi = 0; mi < 2; mi++) {
                uint32_t ao = a_lane + (uint32_t)(mi * 16 * A_STRIDE + ks * 32);
                ldsm_x4(ah[mi], sm + OFF_AH + ao);
                ldsm_x4(al[mi], sm + OFF_AL + ao);
            }
#pragma unroll
            for (int ni = 0; ni < 4; ni++) {
                const uint32_t bo = b_lane + (uint32_t)(ks * 16 * B_STRIDE + ni * 32);
                uint32_t b[4];
                ldsm_x4t(b, sm + OFF_BH + bo);
#pragma unroll
                for (int mi = 0; mi < 2; mi++) {
                    mma_bf16(acc[mi][ni * 2 + 0], ah[mi], b[0], b[1]);   // hi*hi
                    mma_bf16(acc[mi][ni * 2 + 1], ah[mi], b[2], b[3]);
                    mma_bf16(acc[mi][ni * 2 + 0], al[mi], b[0], b[1]);   // lo*hi
                    mma_bf16(acc[mi][ni * 2 + 1], al[mi], b[2], b[3]);
                }
                ldsm_x4t(b, sm + OFF_BL + bo);
#pragma unroll
                for (int mi = 0; mi < 2; mi++) {
                    mma_bf16(acc[mi][ni * 2 + 0], ah[mi], b[0], b[1]);   // hi*lo
                    mma_bf16(acc[mi][ni * 2 + 1], ah[mi], b[2], b[3]);
                }
            }
        }
        __syncthreads();
    }

    // ---- epilogue ----
    const int g = lane >> 2;          // 0..7
    const int tg = lane & 3;          // 0..3
#pragma unroll
    for (int mi = 0; mi < 2; mi++) {
        const int r0 = row_base + warp_m * 32 + mi * 16 + g;
        const int r1 = r0 + 8;
        float w0 = 0.0f, w1 = 0.0f;
        if (EPI == 2) { w0 = wmix[r0]; w1 = wmix[r1]; }
#pragma unroll
        for (int nj = 0; nj < 8; nj++) {
            const int gcol = col_base + warp_n * 64 + nj * 8 + tg * 2;
            const float b0 = bias[gcol], b1 = bias[gcol + 1];
            float v00 = acc[mi][nj][0] + b0, v01 = acc[mi][nj][1] + b1;
            float v10 = acc[mi][nj][2] + b0, v11 = acc[mi][nj][3] + b1;
            if (EPI == 1) {
                v00 = gelu_exact(v00); v01 = gelu_exact(v01);
                v10 = gelu_exact(v10); v11 = gelu_exact(v11);
            }
            if (EPI == 2) {
                float2 xo0 = *(const float2*)&xold[(size_t)r0 * N + gcol];
                float2 xo1 = *(const float2*)&xold[(size_t)r1 * N + gcol];
                v00 = w0 * v00 + (1.0f - w0) * xo0.x;
                v01 = w0 * v01 + (1.0f - w0) * xo0.y;
                v10 = w1 * v10 + (1.0f - w1) * xo1.x;
                v11 = w1 * v11 + (1.0f - w1) * xo1.y;
            }
            *(float2*)&C[(size_t)r0 * N + gcol] = make_float2(v00, v01);
            *(float2*)&C[(size_t)r1 * N + gcol] = make_float2(v10, v11);
        }
    }
}

// ---------------------------------------------------------------------------
// Router head GEMV + ACT state update (one warp per token)
// ---------------------------------------------------------------------------
__global__ void router_act_kernel(const float* __restrict__ rh,
                                  const float* __restrict__ Rw2i,
                                  const float* __restrict__ Rb2i)
{
    const int warp = threadIdx.x >> 5;
    const int lane = threadIdx.x & 31;
    const int t = blockIdx.x * 8 + warp;
    if (t >= M_) return;

    const float* r = rh + (size_t)t * HALF_;
    float s = 0.0f;
#pragma unroll
    for (int k = lane; k < HALF_; k += 32) s += r[k] * Rw2i[k];
#pragma unroll
    for (int o = 16; o > 0; o >>= 1) s += __shfl_xor_sync(0xffffffffu, s, o);

    if (lane == 0) {
        const float logit = s + Rb2i[0];
        const float p = 1.0f / (1.0f + expf(-logit));
        const float cum = g_cum[t];
        const float still = g_still[t];
        const float rem = fmaxf(1.0f - cum, 0.0f);
        const bool halt = (cum + p >= ACT_TAU);
        const float w = (halt ? rem : p) * still;
        g_w[t] = w;
        g_cum[t] = cum + w;
        g_wsum[t] += w;
        g_still[t] = halt ? 0.0f : still;
    }
}

__global__ void init_state_kernel()
{
    const int t = blockIdx.x * 256 + threadIdx.x;
    if (t < M_) {
        g_cum[t] = 0.0f;
        g_still[t] = 1.0f;
        g_wsum[t] = 1.0f;
    }
}

__global__ void budget_kernel(float* __restrict__ out)
{
    __shared__ float sh[256];
    float s = 0.0f;
    for (int t = threadIdx.x; t < M_; t += 256) s += g_wsum[t];
    sh[threadIdx.x] = s;
    __syncthreads();
#pragma unroll
    for (int o = 128; o > 0; o >>= 1) {
        if (threadIdx.x < o) sh[threadIdx.x] += sh[threadIdx.x + o];
        __syncthreads();
    }
    if (threadIdx.x == 0) {
        const float avg = sh[0] / (float)M_;
        const float d = avg - TARGET_DEPTH;
        const float rl = d > 0.0f ? d : 0.0f;
        out[0] = BUDGET_WEIGHT * rl * rl;
    }
}

// ---------------------------------------------------------------------------
// Launch
// ---------------------------------------------------------------------------
static void launch_tgemm(int epi, const float* A, const float* W,
                         const float* bias, float* C, int M, int N, int K,
                         const float* wmix, const float* xold)
{
    dim3 grid(N / TBN, M / TBM);
    dim3 blk(256);
    switch (epi) {
        case 0: tgemm<0><<<grid, blk, SMEM_BYTES>>>(A, W, bias, C, M, N, K, wmix, xold); break;
        case 1: tgemm<1><<<grid, blk, SMEM_BYTES>>>(A, W, bias, C, M, N, K, wmix, xold); break;
        default: tgemm<2><<<grid, blk, SMEM_BYTES>>>(A, W, bias, C, M, N, K, wmix, xold); break;
    }
}

extern "C" void kernel_launch(void* const* d_in, const int* in_sizes, int n_in,
                              void* d_out, int out_size)
{
    const float* x_in = (const float*)d_in[0];
    const float* Wb1  = (const float*)d_in[1];
    const float* bb1  = (const float*)d_in[2];
    const float* Wb2  = (const float*)d_in[3];
    const float* bb2  = (const float*)d_in[4];
    const float* Rw1  = (const float*)d_in[5];  // (3, 1025, 512)
    const float* Rb1  = (const float*)d_in[6];  // (3, 512)
    const float* Rw2  = (const float*)d_in[7];  // (3, 512, 1)
    const float* Rb2  = (const float*)d_in[8];  // (3, 1)
    float* out = (float*)d_out;

    float *gh, *gx, *grh, *gw;
    cudaGetSymbolAddress((void**)&gh,  g_h);
    cudaGetSymbolAddress((void**)&gx,  g_x);
    cudaGetSymbolAddress((void**)&grh, g_rh);
    cudaGetSymbolAddress((void**)&gw,  g_w);

    init_state_kernel<<<M_ / 256, 256>>>();

    // Mandatory first body pass
    launch_tgemm(1, x_in, Wb1, bb1, gh, M_, DFF_, H_, nullptr, nullptr);
    launch_tgemm(0, gh, Wb2, bb2, gx, M_, H_, DFF_, nullptr, nullptr);

    for (int i = 0; i < 3; i++) {
        // Router (zero-feature row of Rw1 multiplies zero -> K = H)
        const float* Rw1i = Rw1 + (size_t)i * 1025 * HALF_;
        const float* Rb1i = Rb1 + (size_t)i * HALF_;
        launch_tgemm(1, gx, Rw1i, Rb1i, grh, M_, HALF_, H_, nullptr, nullptr);
        router_act_kernel<<<M_ / 8, 256>>>(grh, Rw2 + (size_t)i * HALF_, Rb2 + i);

        // Body + fused ACT soft mix
        launch_tgemm(1, gx, Wb1, bb1, gh, M_, DFF_, H_, nullptr, nullptr);
        float* dst = (i == 2) ? out : gx;
        launch_tgemm(2, gh, Wb2, bb2, dst, M_, H_, DFF_, gw, gx);
    }

    if (out_size > (int)((size_t)M_ * H_))
        budget_kernel<<<1, 256>>>(out + (size_t)M_ * H_);
}